// round 16
// baseline (speedup 1.0000x reference)
#include <cuda_runtime.h>
#include <cuda_fp16.h>
#include <math.h>

#define NN 50000
#define NN2 100000
#define NE 800000
#define NE2 1600000
#define FIN 64
#define HD 96
#define NG 256
#define SCB 512
#define NSCB2 ((NN2 + SCB - 1) / SCB)   // 196

// weight pack offsets (halves): [L0s0,L0s1, L1s0,L1s1, L2s0,L2s1], transposed [n][k]
#define WOFF_L0 0
#define WOFF_L1 12288            // 2*64*96
#define WOFF_L2 30720            // + 2*96*96
#define WTOT    49152            // + 2*96*96

// ---------------- scratch (device globals; no runtime allocation) -----------
__device__ __align__(16) __half g_hh[NN2 * HD];   // layer outputs, fp16
__device__ __align__(16) __half g_xh[NN2 * FIN];  // input features, fp16
__device__ __align__(16) __half g_aggh[NN2 * HD]; // gather outputs, fp16
__device__ __align__(16) __half g_whi[WTOT];      // weights hi, fp16, [n][k]
__device__ __align__(16) __half g_wlo[WTOT];      // weights lo (residual)
__device__ float g_dinv[NN2];
__device__ int   g_deg[NN2];
__device__ int   g_coff[NN2 + 1];
__device__ int   g_cur[NN2];
__device__ __align__(8) int2 g_edge[NE2];         // (local src, norm-bits)
__device__ int   g_bsum[256];
__device__ float g_gate[NN2];

// zero-initialized-per-iteration block (single memset)
struct __align__(16) ZeroBlk {
    float gden[2][NG];
    int   cnt[2][NG];
    float att[2][NG * FIN];
    float pool[2][NG * HD];
};
__device__ ZeroBlk g_z;

// ---------------- helpers ----------------------------------------------------
__device__ __forceinline__ void red4(float* p, float4 v) {
    asm volatile("red.global.add.v4.f32 [%0], {%1,%2,%3,%4};"
                 :: "l"(p), "f"(v.x), "f"(v.y), "f"(v.z), "f"(v.w) : "memory");
}
__device__ __forceinline__ void red2(float* p, float a, float b) {
    asm volatile("red.global.add.v2.f32 [%0], {%1,%2};"
                 :: "l"(p), "f"(a), "f"(b) : "memory");
}

__device__ __forceinline__ void mma16816(float* c, const unsigned* a, unsigned b0, unsigned b1) {
    asm volatile(
        "mma.sync.aligned.m16n8k16.row.col.f32.f16.f16.f32 "
        "{%0,%1,%2,%3}, {%4,%5,%6,%7}, {%8,%9}, {%0,%1,%2,%3};"
        : "+f"(c[0]), "+f"(c[1]), "+f"(c[2]), "+f"(c[3])
        : "r"(a[0]), "r"(a[1]), "r"(a[2]), "r"(a[3]), "r"(b0), "r"(b1));
}

// acc[0..7] (half2) += w2 * (16 halves in two int4) — pure HFMA2
__device__ __forceinline__ void fma16h(int4 r0, int4 r1, __half2 w2, __half2* acc) {
    __half2* h0 = reinterpret_cast<__half2*>(&r0);
    __half2* h1 = reinterpret_cast<__half2*>(&r1);
    acc[0] = __hfma2(h0[0], w2, acc[0]);
    acc[1] = __hfma2(h0[1], w2, acc[1]);
    acc[2] = __hfma2(h0[2], w2, acc[2]);
    acc[3] = __hfma2(h0[3], w2, acc[3]);
    acc[4] = __hfma2(h1[0], w2, acc[4]);
    acc[5] = __hfma2(h1[1], w2, acc[5]);
    acc[6] = __hfma2(h1[2], w2, acc[6]);
    acc[7] = __hfma2(h1[3], w2, acc[7]);
}

// ---------------- weight preconversion: fp32 [k][n] -> hi/lo fp16 [n][k] -------
__global__ void k_prepw(const float* __restrict__ Wp0, const float* __restrict__ Wd0,
                        const float* __restrict__ Wp1, const float* __restrict__ Wd1,
                        const float* __restrict__ Wp2, const float* __restrict__ Wd2) {
    int idx = blockIdx.x * blockDim.x + threadIdx.x;
    if (idx >= WTOT) return;
    const float* W;
    int K, base, e;
    if (idx < WOFF_L1) {
        int t = idx - WOFF_L0;  K = 64;
        int side = t / 6144;    e = t - side * 6144;
        W = side ? Wd0 : Wp0;   base = WOFF_L0 + side * 6144;
    } else if (idx < WOFF_L2) {
        int t = idx - WOFF_L1;  K = 96;
        int side = t / 9216;    e = t - side * 9216;
        W = side ? Wd1 : Wp1;   base = WOFF_L1 + side * 9216;
    } else {
        int t = idx - WOFF_L2;  K = 96;
        int side = t / 9216;    e = t - side * 9216;
        W = side ? Wd2 : Wp2;   base = WOFF_L2 + side * 9216;
    }
    int k = e / HD, n = e - k * HD;
    float w = __ldg(&W[k * HD + n]);
    __half hi = __float2half_rn(w);
    __half lo = __float2half_rn(w - __half2float(hi));
    g_whi[base + n * K + k] = hi;
    g_wlo[base + n * K + k] = lo;
}

// ---------------- input conversion ---------------------------------------------
__global__ void k_tohalf(const float4* __restrict__ xp, const float4* __restrict__ xd) {
    int idx = blockIdx.x * blockDim.x + threadIdx.x;      // NN2 * 16
    if (idx >= NN2 * 16) return;
    int n = idx >> 4;
    int side = (n >= NN);
    int nl = n - side * NN;
    float4 v = __ldg(&(side ? xd : xp)[nl * 16 + (idx & 15)]);
    __half2 h0 = __floats2half2_rn(v.x, v.y);
    __half2 h1 = __floats2half2_rn(v.z, v.w);
    uint2 u;
    u.x = *(unsigned*)&h0; u.y = *(unsigned*)&h1;
    ((uint2*)g_xh)[idx] = u;
}

__global__ void k_deg(const int* __restrict__ eip, const int* __restrict__ eid) {
    int e = blockIdx.x * blockDim.x + threadIdx.x;
    if (e >= NE2) return;
    int side = (e >= NE);
    int el = e - side * NE;
    const int* ei = side ? eid : eip;
    atomicAdd(&g_deg[side * NN + ei[NE + el]], 1);
}

// ---------------- CSR build ----------------------------------------------------
__global__ void k_scan1() {
    __shared__ int s[SCB];
    int i = blockIdx.x * SCB + threadIdx.x;
    s[threadIdx.x] = (i < NN2) ? g_deg[i] : 0;
    __syncthreads();
    for (int o = SCB / 2; o > 0; o >>= 1) {
        if (threadIdx.x < o) s[threadIdx.x] += s[threadIdx.x + o];
        __syncthreads();
    }
    if (threadIdx.x == 0) g_bsum[blockIdx.x] = s[0];
}

__global__ void k_scan3() {
    __shared__ int sb[SCB];
    int t = threadIdx.x;
    sb[t] = (t < blockIdx.x) ? g_bsum[t] : 0;
    __syncthreads();
    for (int o = SCB / 2; o > 0; o >>= 1) {
        if (t < o) sb[t] += sb[t + o];
        __syncthreads();
    }
    int boff = sb[0];
    __syncthreads();
    int i = blockIdx.x * SCB + t;
    int v = (i < NN2) ? g_deg[i] : 0;
    sb[t] = v;
    __syncthreads();
    for (int o = 1; o < SCB; o <<= 1) {
        int a = (t >= o) ? sb[t - o] : 0;
        __syncthreads();
        sb[t] += a;
        __syncthreads();
    }
    if (i < NN2) {
        int off = boff + sb[t] - v;                 // exclusive
        g_coff[i] = off;
        g_cur[i] = off;
        g_dinv[i] = rsqrtf((float)v + 1.0f);
    }
    if (blockIdx.x == NSCB2 - 1 && t == SCB - 1) g_coff[NN2] = boff + sb[t];
}

__global__ void k_csrfill(const int* __restrict__ eip, const int* __restrict__ eid) {
    int e = blockIdx.x * blockDim.x + threadIdx.x;
    if (e >= NE2) return;
    int side = (e >= NE);
    int el = e - side * NE;
    const int* ei = side ? eid : eip;
    int s = ei[el], d = ei[NE + el];
    int base = side * NN;
    float norm = g_dinv[base + s] * g_dinv[base + d];
    int slot = atomicAdd(&g_cur[base + d], 1);
    g_edge[slot] = make_int2(s, __float_as_int(norm));
}

// ---------------- attention gate (both sides) ----------------------------------
__global__ void k_gate(const float* __restrict__ xp, const float* __restrict__ xd,
                       const int* __restrict__ bp, const int* __restrict__ bd,
                       const float* __restrict__ gW1, const float* __restrict__ gb1,
                       const float* __restrict__ gW2, const float* __restrict__ gb2) {
    int lane = threadIdx.x & 31;
    int n = blockIdx.x * (blockDim.x >> 5) + (threadIdx.x >> 5);
    if (n >= NN2) return;
    int side = (n >= NN);
    int nl = n - side * NN;
    const float* x = side ? xd : xp;
    const int* batch = side ? bd : bp;
    float xa = x[nl * FIN + lane];
    float xb = x[nl * FIN + 32 + lane];
    float acc0 = gb1[lane];
    float acc1 = gb1[lane + 32];
#pragma unroll
    for (int k = 0; k < FIN; k++) {
        float xk = __shfl_sync(0xffffffffu, (k < 32) ? xa : xb, k & 31);
        acc0 += xk * gW1[k * FIN + lane];
        acc1 += xk * gW1[k * FIN + lane + 32];
    }
    float h = fmaxf(acc0, 0.f) * gW2[lane] + fmaxf(acc1, 0.f) * gW2[lane + 32];
#pragma unroll
    for (int o = 16; o > 0; o >>= 1) h += __shfl_down_sync(0xffffffffu, h, o);
    if (lane == 0) {
        float e = expf(h + gb2[0]);        // gates tiny: no max-shift needed
        g_gate[n] = e;
        int b = batch[nl];
        atomicAdd(&g_z.gden[side][b], e);
        atomicAdd(&g_z.cnt[side][b], 1);
    }
}

__global__ void k_attpool(const float* __restrict__ xp, const float* __restrict__ xd,
                          const int* __restrict__ bp, const int* __restrict__ bd) {
    int idx = blockIdx.x * blockDim.x + threadIdx.x;     // NN2 * 16
    if (idx >= NN2 * (FIN / 4)) return;
    int n = idx >> 4, j = idx & 15;
    int side = (n >= NN);
    int nl = n - side * NN;
    int b = side ? bd[nl] : bp[nl];
    float alpha = g_gate[n] / g_z.gden[side][b];
    const float4* x4 = side ? (const float4*)xd : (const float4*)xp;
    float4 v = __ldg(&x4[nl * (FIN / 4) + j]);
    v.x *= alpha; v.y *= alpha; v.z *= alpha; v.w *= alpha;
    red4(&g_z.att[side][b * FIN + j * 4], v);
}

// ---------------- fp16 CSR gather (one side), 32B/thread, HFMA2 ----------------
// U = K8/2 thread-chunks per row; each thread covers 2 int4 (16 halves).
__global__ void k_gatherh(const int4* __restrict__ f16, int K8, int side) {
    const int U = K8 >> 1;
    int idx = blockIdx.x * blockDim.x + threadIdx.x;     // NN * U
    if (idx >= NN * U) return;
    int nl = idx / U, j2 = (idx - nl * U) * 2;
    int base = side * NN;
    int n = base + nl;
    float dv = g_dinv[n];
    __half2 acc[8];
    {
        __half2 s2 = __float2half2_rn(dv * dv);
        int4 r0 = __ldg(&f16[(size_t)n * K8 + j2]);
        int4 r1 = __ldg(&f16[(size_t)n * K8 + j2 + 1]);
        __half2* h0 = reinterpret_cast<__half2*>(&r0);
        __half2* h1 = reinterpret_cast<__half2*>(&r1);
        acc[0] = __hmul2(h0[0], s2); acc[1] = __hmul2(h0[1], s2);
        acc[2] = __hmul2(h0[2], s2); acc[3] = __hmul2(h0[3], s2);
        acc[4] = __hmul2(h1[0], s2); acc[5] = __hmul2(h1[1], s2);
        acc[6] = __hmul2(h1[2], s2); acc[7] = __hmul2(h1[3], s2);
    }
    int p = __ldg(&g_coff[n]);
    int end = __ldg(&g_coff[n + 1]);
    for (; p + 3 < end; p += 4) {
        int2 e0 = __ldg(&g_edge[p]);
        int2 e1 = __ldg(&g_edge[p + 1]);
        int2 e2 = __ldg(&g_edge[p + 2]);
        int2 e3 = __ldg(&g_edge[p + 3]);
        size_t r0 = (size_t)(base + e0.x) * K8 + j2;
        size_t r1 = (size_t)(base + e1.x) * K8 + j2;
        size_t r2 = (size_t)(base + e2.x) * K8 + j2;
        size_t r3 = (size_t)(base + e3.x) * K8 + j2;
        int4 a0 = __ldg(&f16[r0]),     b0 = __ldg(&f16[r0 + 1]);
        int4 a1 = __ldg(&f16[r1]),     b1 = __ldg(&f16[r1 + 1]);
        int4 a2 = __ldg(&f16[r2]),     b2 = __ldg(&f16[r2 + 1]);
        int4 a3 = __ldg(&f16[r3]),     b3 = __ldg(&f16[r3 + 1]);
        fma16h(a0, b0, __float2half2_rn(__int_as_float(e0.y)), acc);
        fma16h(a1, b1, __float2half2_rn(__int_as_float(e1.y)), acc);
        fma16h(a2, b2, __float2half2_rn(__int_as_float(e2.y)), acc);
        fma16h(a3, b3, __float2half2_rn(__int_as_float(e3.y)), acc);
    }
    for (; p < end; p++) {
        int2 e0 = __ldg(&g_edge[p]);
        size_t r0 = (size_t)(base + e0.x) * K8 + j2;
        int4 a0 = __ldg(&f16[r0]), b0 = __ldg(&f16[r0 + 1]);
        fma16h(a0, b0, __float2half2_rn(__int_as_float(e0.y)), acc);
    }
    int4 o0, o1;
    o0.x = *(int*)&acc[0]; o0.y = *(int*)&acc[1];
    o0.z = *(int*)&acc[2]; o0.w = *(int*)&acc[3];
    o1.x = *(int*)&acc[4]; o1.y = *(int*)&acc[5];
    o1.z = *(int*)&acc[6]; o1.w = *(int*)&acc[7];
    ((int4*)g_aggh)[(size_t)n * K8 + j2]     = o0;
    ((int4*)g_aggh)[(size_t)n * K8 + j2 + 1] = o1;
}

// ---------------- HMMA GEMM (one side): out = aggh @ W + b ----------------------
__global__ void __launch_bounds__(256) k_gemm_mma(
        int woff, const float* __restrict__ bias,
        int K, int reluOut, int fusePool,
        const int* __restrict__ batch, int side) {
    extern __shared__ __half sm[];
    const int KS = K + 8;
    __half* As  = sm;                     // 128 x KS
    __half* Bhi = As + 128 * KS;          // 96 x KS  ([n][k])
    __half* Blo = Bhi + 96 * KS;
    const int rowBase = blockIdx.x * 128;
    const int tid = threadIdx.x;
    const int K8 = K >> 3;

    // copy preconverted weights (int4 = 8 halves)
    const int4* Wh4 = (const int4*)(g_whi + woff + side * (HD * K));
    const int4* Wl4 = (const int4*)(g_wlo + woff + side * (HD * K));
    for (int i = tid; i < HD * K8; i += 256) {
        int r = i / K8, j = i - r * K8;
        *(int4*)&Bhi[r * KS + j * 8] = __ldg(&Wh4[i]);
        *(int4*)&Blo[r * KS + j * 8] = __ldg(&Wl4[i]);
    }
    const int4* Ah = (const int4*)g_aggh;
    for (int i = tid; i < 128 * K8; i += 256) {
        int r = i / K8, j = i - r * K8;
        int row = rowBase + r;
        int4 v = make_int4(0, 0, 0, 0);
        if (row < NN) v = __ldg(&Ah[(size_t)(side * NN + row) * K8 + j]);
        *(int4*)&As[r * KS + j * 8] = v;
    }
    __syncthreads();

    const int warp = tid >> 5;
    const int lane = tid & 31;
    const int g = lane >> 2;
    const int tg = lane & 3;
    const int warpRow = warp * 16;

    float c[12][4];
#pragma unroll
    for (int nt = 0; nt < 12; nt++)
#pragma unroll
        for (int q = 0; q < 4; q++) c[nt][q] = 0.f;

    const int nk = K >> 4;
    for (int ks = 0; ks < nk; ks++) {
        unsigned a[4];
        const __half* arow0 = &As[(warpRow + g) * KS + ks * 16 + tg * 2];
        const __half* arow1 = arow0 + 8 * KS;
        a[0] = *(const unsigned*)arow0;
        a[1] = *(const unsigned*)arow1;
        a[2] = *(const unsigned*)(arow0 + 8);
        a[3] = *(const unsigned*)(arow1 + 8);
#pragma unroll
        for (int nt = 0; nt < 12; nt++) {
            const __half* brow = &Bhi[(nt * 8 + g) * KS + ks * 16 + tg * 2];
            unsigned b0 = *(const unsigned*)brow;
            unsigned b1 = *(const unsigned*)(brow + 8);
            mma16816(c[nt], a, b0, b1);
            const __half* brl = &Blo[(nt * 8 + g) * KS + ks * 16 + tg * 2];
            unsigned l0 = *(const unsigned*)brl;
            unsigned l1 = *(const unsigned*)(brl + 8);
            mma16816(c[nt], a, l0, l1);
        }
    }

    int row0 = rowBase + warpRow + g;
    int row1 = row0 + 8;
#pragma unroll
    for (int nt = 0; nt < 12; nt++) {
        int col = nt * 8 + tg * 2;
        float bx = __ldg(&bias[col]);
        float by = __ldg(&bias[col + 1]);
        float v00 = c[nt][0] + bx, v01 = c[nt][1] + by;
        float v10 = c[nt][2] + bx, v11 = c[nt][3] + by;
        if (!fusePool) {
            if (reluOut) {
                v00 = fmaxf(v00, 0.f); v01 = fmaxf(v01, 0.f);
                v10 = fmaxf(v10, 0.f); v11 = fmaxf(v11, 0.f);
            }
            if (row0 < NN) {
                __half2 h = __floats2half2_rn(v00, v01);
                *(unsigned*)&g_hh[(size_t)(side * NN + row0) * HD + col] = *(unsigned*)&h;
            }
            if (row1 < NN) {
                __half2 h = __floats2half2_rn(v10, v11);
                *(unsigned*)&g_hh[(size_t)(side * NN + row1) * HD + col] = *(unsigned*)&h;
            }
        } else {
            if (row0 < NN) red2(&g_z.pool[side][batch[row0] * HD + col], v00, v01);
            if (row1 < NN) red2(&g_z.pool[side][batch[row1] * HD + col], v10, v11);
        }
    }
}

// ---------------- final MLP ---------------------------------------------------
__global__ void k_final(const float* __restrict__ lW0, const float* __restrict__ lb0,
                        const float* __restrict__ lW1, const float* __restrict__ lb1,
                        float* __restrict__ out) {
    int g = blockIdx.x;
    int j = threadIdx.x;                                 // 96 threads
    __shared__ float cat[2 * HD + 2 * FIN];              // 320
    __shared__ float red[HD];
    for (int i = j; i < 2 * HD + 2 * FIN; i += HD) {
        float v;
        if (i < HD)            v = g_z.pool[0][g * HD + i] / fmaxf((float)g_z.cnt[0][g], 1.f);
        else if (i < 2 * HD)   v = g_z.pool[1][g * HD + (i - HD)] / fmaxf((float)g_z.cnt[1][g], 1.f);
        else if (i < 2 * HD + FIN) v = g_z.att[0][g * FIN + (i - 2 * HD)];
        else                   v = g_z.att[1][g * FIN + (i - 2 * HD - FIN)];
        cat[i] = v;
    }
    __syncthreads();
    float acc = lb0[j];
#pragma unroll 8
    for (int i = 0; i < 2 * HD + 2 * FIN; i++)
        acc += cat[i] * lW0[i * HD + j];
    red[j] = fmaxf(acc, 0.f) * lW1[j];
    __syncthreads();
    if (j == 0) {
        float s = lb1[0];
        for (int t = 0; t < HD; t++) s += red[t];
        out[g] = s;
    }
}

// ---------------- host launcher ----------------------------------------------
extern "C" void kernel_launch(void* const* d_in, const int* in_sizes, int n_in,
                              void* d_out, int out_size) {
    const float* xp  = (const float*)d_in[0];
    const float* xd  = (const float*)d_in[1];
    const int*   eip = (const int*)d_in[4];
    const int*   eid = (const int*)d_in[5];
    const int*   bp  = (const int*)d_in[6];
    const int*   bd  = (const int*)d_in[7];
    const float* Wp0 = (const float*)d_in[8],  *bp0 = (const float*)d_in[9];
    const float* Wp1 = (const float*)d_in[10], *bp1 = (const float*)d_in[11];
    const float* Wp2 = (const float*)d_in[12], *bp2 = (const float*)d_in[13];
    const float* Wd0 = (const float*)d_in[14], *bd0 = (const float*)d_in[15];
    const float* Wd1 = (const float*)d_in[16], *bd1 = (const float*)d_in[17];
    const float* Wd2 = (const float*)d_in[18], *bd2 = (const float*)d_in[19];
    const float* gW1 = (const float*)d_in[20], *gb1 = (const float*)d_in[21];
    const float* gW2 = (const float*)d_in[22], *gb2 = (const float*)d_in[23];
    const float* lW0 = (const float*)d_in[24], *lb0 = (const float*)d_in[25];
    const float* lW1 = (const float*)d_in[26], *lb1 = (const float*)d_in[27];

    const int TB = 256;
    const int GB_E2 = (NE2 + TB - 1) / TB;
    const int GB_C16 = (NN2 * 16 + TB - 1) / TB;
    const int GB_S4  = (NN * 4 + TB - 1) / TB;       // per-side gather U=4 (K=64)
    const int GB_S6  = (NN * 6 + TB - 1) / TB;       // per-side gather U=6 (K=96)
    const int GEMM_GRID = 391;                       // per-side tiles
    const int SMEM96 = (128 + 96 + 96) * (96 + 8) * 2;   // 66560 B
    const int SMEM64 = (128 + 96 + 96) * (64 + 8) * 2;   // 46080 B

    static cudaStream_t sB = nullptr, sC = nullptr;
    static cudaEvent_t ev1 = nullptr, evT = nullptr, evB = nullptr,
                       evCSR = nullptr, evC = nullptr;
    static int inited = 0;
    if (!inited) {
        cudaFuncSetAttribute(k_gemm_mma, cudaFuncAttributeMaxDynamicSharedMemorySize, SMEM96);
        cudaStreamCreateWithFlags(&sB, cudaStreamNonBlocking);
        cudaStreamCreateWithFlags(&sC, cudaStreamNonBlocking);
        cudaEventCreateWithFlags(&ev1, cudaEventDisableTiming);
        cudaEventCreateWithFlags(&evT, cudaEventDisableTiming);
        cudaEventCreateWithFlags(&evB, cudaEventDisableTiming);
        cudaEventCreateWithFlags(&evCSR, cudaEventDisableTiming);
        cudaEventCreateWithFlags(&evC, cudaEventDisableTiming);
        inited = 1;
    }

    void* xh_dev = nullptr;  cudaGetSymbolAddress(&xh_dev, g_xh);
    void* hh_dev = nullptr;  cudaGetSymbolAddress(&hh_dev, g_hh);
    void* deg_dev = nullptr; cudaGetSymbolAddress(&deg_dev, g_deg);
    void* z_dev = nullptr;   cudaGetSymbolAddress(&z_dev, g_z);

    // ---- fork ----
    cudaEventRecord(ev1, 0);
    cudaStreamWaitEvent(sB, ev1, 0);
    cudaStreamWaitEvent(sC, ev1, 0);

    // stream B: zero-init, weight prep + tohalf, then gate+attpool
    cudaMemsetAsync(z_dev, 0, sizeof(ZeroBlk), sB);
    k_prepw<<<(WTOT + TB - 1) / TB, TB, 0, sB>>>(Wp0, Wd0, Wp1, Wd1, Wp2, Wd2);
    k_tohalf<<<GB_C16, TB, 0, sB>>>((const float4*)xp, (const float4*)xd);
    cudaEventRecord(evT, sB);                 // side chains need prepw+tohalf
    k_gate<<<(NN2 + 7) / 8, 256, 0, sB>>>(xp, xd, bp, bd, gW1, gb1, gW2, gb2);
    k_attpool<<<GB_C16, TB, 0, sB>>>(xp, xd, bp, bd);
    cudaEventRecord(evB, sB);                 // k_final needs this

    // stream A (default): CSR build (both sides)
    cudaMemsetAsync(deg_dev, 0, NN2 * sizeof(int), 0);
    k_deg<<<GB_E2, TB>>>(eip, eid);
    k_scan1<<<NSCB2, SCB>>>();
    k_scan3<<<NSCB2, SCB>>>();
    k_csrfill<<<GB_E2, TB>>>(eip, eid);
    cudaEventRecord(evCSR, 0);

    // side-p chain on stream A (needs tohalf/prepw from B)
    cudaStreamWaitEvent(0, evT, 0);
    k_gatherh<<<GB_S4, TB>>>((const int4*)xh_dev, 8, 0);
    k_gemm_mma<<<GEMM_GRID, 256, SMEM64>>>(WOFF_L0, bp0, 64, 1, 0, bp, 0);
    k_gatherh<<<GB_S6, TB>>>((const int4*)hh_dev, 12, 0);
    k_gemm_mma<<<GEMM_GRID, 256, SMEM96>>>(WOFF_L1, bp1, 96, 1, 0, bp, 0);
    k_gatherh<<<GB_S6, TB>>>((const int4*)hh_dev, 12, 0);
    k_gemm_mma<<<GEMM_GRID, 256, SMEM96>>>(WOFF_L2, bp2, 96, 0, 1, bp, 0);

    // side-d chain on stream C (needs CSR from A + tohalf/prepw from B)
    cudaStreamWaitEvent(sC, evCSR, 0);
    cudaStreamWaitEvent(sC, evT, 0);
    k_gatherh<<<GB_S4, TB, 0, sC>>>((const int4*)xh_dev, 8, 1);
    k_gemm_mma<<<GEMM_GRID, 256, SMEM64, sC>>>(WOFF_L0, bd0, 64, 1, 0, bd, 1);
    k_gatherh<<<GB_S6, TB, 0, sC>>>((const int4*)hh_dev, 12, 1);
    k_gemm_mma<<<GEMM_GRID, 256, SMEM96, sC>>>(WOFF_L1, bd1, 96, 1, 0, bd, 1);
    k_gatherh<<<GB_S6, TB, 0, sC>>>((const int4*)hh_dev, 12, 1);
    k_gemm_mma<<<GEMM_GRID, 256, SMEM96, sC>>>(WOFF_L2, bd2, 96, 0, 1, bd, 1);
    cudaEventRecord(evC, sC);

    // join: k_final needs side-p (stream A order), side-d (evC), attpool (evB)
    cudaStreamWaitEvent(0, evC, 0);
    cudaStreamWaitEvent(0, evB, 0);
    k_final<<<NG, HD>>>(lW0, lb0, lW1, lb1, (float*)d_out);
}

// round 17
// speedup vs baseline: 1.0065x; 1.0065x over previous
#include <cuda_runtime.h>
#include <cuda_fp16.h>
#include <math.h>

#define NN 50000
#define NN2 100000
#define NE 800000
#define NE2 1600000
#define FIN 64
#define HD 96
#define NG 256
#define SCB 512
#define NSCB ((NN + SCB - 1) / SCB)     // 98 blocks per side

// weight pack offsets (halves): [L0s0,L0s1, L1s0,L1s1, L2s0,L2s1], transposed [n][k]
#define WOFF_L0 0
#define WOFF_L1 12288            // 2*64*96
#define WOFF_L2 30720            // + 2*96*96
#define WTOT    49152            // + 2*96*96

// ---------------- scratch (device globals; no runtime allocation) -----------
__device__ __align__(16) __half g_hh[NN2 * HD];   // layer outputs, fp16
__device__ __align__(16) __half g_xh[NN2 * FIN];  // input features, fp16
__device__ __align__(16) __half g_aggh[NN2 * HD]; // gather outputs, fp16
__device__ __align__(16) __half g_whi[WTOT];      // weights hi, fp16, [n][k]
__device__ __align__(16) __half g_wlo[WTOT];      // weights lo (residual)
__device__ float g_dinv[NN2];
__device__ int   g_deg[NN2];
__device__ int   g_coff[2][NN + 1];               // per-side CSR offsets
__device__ int   g_cur[NN2];
__device__ __align__(8) int2 g_edge[NE2];         // per-side halves: [side*NE ...]
__device__ int   g_bsum[2][128];
__device__ float g_gate[NN2];

// zero-initialized-per-iteration block (single memset)
struct __align__(16) ZeroBlk {
    float gden[2][NG];
    int   cnt[2][NG];
    float att[2][NG * FIN];
    float pool[2][NG * HD];
};
__device__ ZeroBlk g_z;

// ---------------- helpers ----------------------------------------------------
__device__ __forceinline__ void red4(float* p, float4 v) {
    asm volatile("red.global.add.v4.f32 [%0], {%1,%2,%3,%4};"
                 :: "l"(p), "f"(v.x), "f"(v.y), "f"(v.z), "f"(v.w) : "memory");
}
__device__ __forceinline__ void red2(float* p, float a, float b) {
    asm volatile("red.global.add.v2.f32 [%0], {%1,%2};"
                 :: "l"(p), "f"(a), "f"(b) : "memory");
}

__device__ __forceinline__ void mma16816(float* c, const unsigned* a, unsigned b0, unsigned b1) {
    asm volatile(
        "mma.sync.aligned.m16n8k16.row.col.f32.f16.f16.f32 "
        "{%0,%1,%2,%3}, {%4,%5,%6,%7}, {%8,%9}, {%0,%1,%2,%3};"
        : "+f"(c[0]), "+f"(c[1]), "+f"(c[2]), "+f"(c[3])
        : "r"(a[0]), "r"(a[1]), "r"(a[2]), "r"(a[3]), "r"(b0), "r"(b1));
}

// acc[0..7] (half2) += w2 * (16 halves in two int4) — pure HFMA2
__device__ __forceinline__ void fma16h(int4 r0, int4 r1, __half2 w2, __half2* acc) {
    __half2* h0 = reinterpret_cast<__half2*>(&r0);
    __half2* h1 = reinterpret_cast<__half2*>(&r1);
    acc[0] = __hfma2(h0[0], w2, acc[0]);
    acc[1] = __hfma2(h0[1], w2, acc[1]);
    acc[2] = __hfma2(h0[2], w2, acc[2]);
    acc[3] = __hfma2(h0[3], w2, acc[3]);
    acc[4] = __hfma2(h1[0], w2, acc[4]);
    acc[5] = __hfma2(h1[1], w2, acc[5]);
    acc[6] = __hfma2(h1[2], w2, acc[6]);
    acc[7] = __hfma2(h1[3], w2, acc[7]);
}

// ---------------- weight preconversion: fp32 [k][n] -> hi/lo fp16 [n][k] -------
__global__ void k_prepw(const float* __restrict__ Wp0, const float* __restrict__ Wd0,
                        const float* __restrict__ Wp1, const float* __restrict__ Wd1,
                        const float* __restrict__ Wp2, const float* __restrict__ Wd2) {
    int idx = blockIdx.x * blockDim.x + threadIdx.x;
    if (idx >= WTOT) return;
    const float* W;
    int K, base, e;
    if (idx < WOFF_L1) {
        int t = idx - WOFF_L0;  K = 64;
        int side = t / 6144;    e = t - side * 6144;
        W = side ? Wd0 : Wp0;   base = WOFF_L0 + side * 6144;
    } else if (idx < WOFF_L2) {
        int t = idx - WOFF_L1;  K = 96;
        int side = t / 9216;    e = t - side * 9216;
        W = side ? Wd1 : Wp1;   base = WOFF_L1 + side * 9216;
    } else {
        int t = idx - WOFF_L2;  K = 96;
        int side = t / 9216;    e = t - side * 9216;
        W = side ? Wd2 : Wp2;   base = WOFF_L2 + side * 9216;
    }
    int k = e / HD, n = e - k * HD;
    float w = __ldg(&W[k * HD + n]);
    __half hi = __float2half_rn(w);
    __half lo = __float2half_rn(w - __half2float(hi));
    g_whi[base + n * K + k] = hi;
    g_wlo[base + n * K + k] = lo;
}

// ---------------- input conversion ---------------------------------------------
__global__ void k_tohalf(const float4* __restrict__ xp, const float4* __restrict__ xd) {
    int idx = blockIdx.x * blockDim.x + threadIdx.x;      // NN2 * 16
    if (idx >= NN2 * 16) return;
    int n = idx >> 4;
    int side = (n >= NN);
    int nl = n - side * NN;
    float4 v = __ldg(&(side ? xd : xp)[nl * 16 + (idx & 15)]);
    __half2 h0 = __floats2half2_rn(v.x, v.y);
    __half2 h1 = __floats2half2_rn(v.z, v.w);
    uint2 u;
    u.x = *(unsigned*)&h0; u.y = *(unsigned*)&h1;
    ((uint2*)g_xh)[idx] = u;
}

// ---------------- per-side CSR build -------------------------------------------
__global__ void k_deg_s(const int* __restrict__ ei, int side) {
    int e = blockIdx.x * blockDim.x + threadIdx.x;
    if (e < NE) atomicAdd(&g_deg[side * NN + ei[NE + e]], 1);
}

__global__ void k_scan1_s(int side) {
    __shared__ int s[SCB];
    int i = blockIdx.x * SCB + threadIdx.x;
    s[threadIdx.x] = (i < NN) ? g_deg[side * NN + i] : 0;
    __syncthreads();
    for (int o = SCB / 2; o > 0; o >>= 1) {
        if (threadIdx.x < o) s[threadIdx.x] += s[threadIdx.x + o];
        __syncthreads();
    }
    if (threadIdx.x == 0) g_bsum[side][blockIdx.x] = s[0];
}

__global__ void k_scan3_s(int side) {
    __shared__ int sb[SCB];
    int t = threadIdx.x;
    sb[t] = (t < blockIdx.x && t < 128) ? g_bsum[side][t] : 0;   // blockIdx.x < 98
    __syncthreads();
    for (int o = SCB / 2; o > 0; o >>= 1) {
        if (t < o) sb[t] += sb[t + o];
        __syncthreads();
    }
    int boff = sb[0];
    __syncthreads();
    int i = blockIdx.x * SCB + t;
    int v = (i < NN) ? g_deg[side * NN + i] : 0;
    sb[t] = v;
    __syncthreads();
    for (int o = 1; o < SCB; o <<= 1) {
        int a = (t >= o) ? sb[t - o] : 0;
        __syncthreads();
        sb[t] += a;
        __syncthreads();
    }
    if (i < NN) {
        int off = boff + sb[t] - v;                 // exclusive, within side
        g_coff[side][i] = off;
        g_cur[side * NN + i] = off;
        g_dinv[side * NN + i] = rsqrtf((float)v + 1.0f);
    }
    if (blockIdx.x == NSCB - 1 && t == SCB - 1) g_coff[side][NN] = boff + sb[t];
}

__global__ void k_csrfill_s(const int* __restrict__ ei, int side) {
    int e = blockIdx.x * blockDim.x + threadIdx.x;
    if (e >= NE) return;
    int s = ei[e], d = ei[NE + e];
    int base = side * NN;
    float norm = g_dinv[base + s] * g_dinv[base + d];
    int slot = atomicAdd(&g_cur[base + d], 1);
    g_edge[side * NE + slot] = make_int2(s, __float_as_int(norm));
}

// ---------------- attention gate (both sides) ----------------------------------
__global__ void k_gate(const float* __restrict__ xp, const float* __restrict__ xd,
                       const int* __restrict__ bp, const int* __restrict__ bd,
                       const float* __restrict__ gW1, const float* __restrict__ gb1,
                       const float* __restrict__ gW2, const float* __restrict__ gb2) {
    int lane = threadIdx.x & 31;
    int n = blockIdx.x * (blockDim.x >> 5) + (threadIdx.x >> 5);
    if (n >= NN2) return;
    int side = (n >= NN);
    int nl = n - side * NN;
    const float* x = side ? xd : xp;
    const int* batch = side ? bd : bp;
    float xa = x[nl * FIN + lane];
    float xb = x[nl * FIN + 32 + lane];
    float acc0 = gb1[lane];
    float acc1 = gb1[lane + 32];
#pragma unroll
    for (int k = 0; k < FIN; k++) {
        float xk = __shfl_sync(0xffffffffu, (k < 32) ? xa : xb, k & 31);
        acc0 += xk * gW1[k * FIN + lane];
        acc1 += xk * gW1[k * FIN + lane + 32];
    }
    float h = fmaxf(acc0, 0.f) * gW2[lane] + fmaxf(acc1, 0.f) * gW2[lane + 32];
#pragma unroll
    for (int o = 16; o > 0; o >>= 1) h += __shfl_down_sync(0xffffffffu, h, o);
    if (lane == 0) {
        float e = expf(h + gb2[0]);        // gates tiny: no max-shift needed
        g_gate[n] = e;
        int b = batch[nl];
        atomicAdd(&g_z.gden[side][b], e);
        atomicAdd(&g_z.cnt[side][b], 1);
    }
}

__global__ void k_attpool(const float* __restrict__ xp, const float* __restrict__ xd,
                          const int* __restrict__ bp, const int* __restrict__ bd) {
    int idx = blockIdx.x * blockDim.x + threadIdx.x;     // NN2 * 16
    if (idx >= NN2 * (FIN / 4)) return;
    int n = idx >> 4, j = idx & 15;
    int side = (n >= NN);
    int nl = n - side * NN;
    int b = side ? bd[nl] : bp[nl];
    float alpha = g_gate[n] / g_z.gden[side][b];
    const float4* x4 = side ? (const float4*)xd : (const float4*)xp;
    float4 v = __ldg(&x4[nl * (FIN / 4) + j]);
    v.x *= alpha; v.y *= alpha; v.z *= alpha; v.w *= alpha;
    red4(&g_z.att[side][b * FIN + j * 4], v);
}

// ---------------- fp16 CSR gather (one side), 32B/thread, HFMA2 ----------------
__global__ void k_gatherh(const int4* __restrict__ f16, int K8, int side) {
    const int U = K8 >> 1;
    int idx = blockIdx.x * blockDim.x + threadIdx.x;     // NN * U
    if (idx >= NN * U) return;
    int nl = idx / U, j2 = (idx - nl * U) * 2;
    int base = side * NN;
    int n = base + nl;
    const int2* edges = g_edge + (size_t)side * NE;
    float dv = g_dinv[n];
    __half2 acc[8];
    {
        __half2 s2 = __float2half2_rn(dv * dv);
        int4 r0 = __ldg(&f16[(size_t)n * K8 + j2]);
        int4 r1 = __ldg(&f16[(size_t)n * K8 + j2 + 1]);
        __half2* h0 = reinterpret_cast<__half2*>(&r0);
        __half2* h1 = reinterpret_cast<__half2*>(&r1);
        acc[0] = __hmul2(h0[0], s2); acc[1] = __hmul2(h0[1], s2);
        acc[2] = __hmul2(h0[2], s2); acc[3] = __hmul2(h0[3], s2);
        acc[4] = __hmul2(h1[0], s2); acc[5] = __hmul2(h1[1], s2);
        acc[6] = __hmul2(h1[2], s2); acc[7] = __hmul2(h1[3], s2);
    }
    int p = __ldg(&g_coff[side][nl]);
    int end = __ldg(&g_coff[side][nl + 1]);
    for (; p + 3 < end; p += 4) {
        int2 e0 = __ldg(&edges[p]);
        int2 e1 = __ldg(&edges[p + 1]);
        int2 e2 = __ldg(&edges[p + 2]);
        int2 e3 = __ldg(&edges[p + 3]);
        size_t r0 = (size_t)(base + e0.x) * K8 + j2;
        size_t r1 = (size_t)(base + e1.x) * K8 + j2;
        size_t r2 = (size_t)(base + e2.x) * K8 + j2;
        size_t r3 = (size_t)(base + e3.x) * K8 + j2;
        int4 a0 = __ldg(&f16[r0]),     b0 = __ldg(&f16[r0 + 1]);
        int4 a1 = __ldg(&f16[r1]),     b1 = __ldg(&f16[r1 + 1]);
        int4 a2 = __ldg(&f16[r2]),     b2 = __ldg(&f16[r2 + 1]);
        int4 a3 = __ldg(&f16[r3]),     b3 = __ldg(&f16[r3 + 1]);
        fma16h(a0, b0, __float2half2_rn(__int_as_float(e0.y)), acc);
        fma16h(a1, b1, __float2half2_rn(__int_as_float(e1.y)), acc);
        fma16h(a2, b2, __float2half2_rn(__int_as_float(e2.y)), acc);
        fma16h(a3, b3, __float2half2_rn(__int_as_float(e3.y)), acc);
    }
    for (; p < end; p++) {
        int2 e0 = __ldg(&edges[p]);
        size_t r0 = (size_t)(base + e0.x) * K8 + j2;
        int4 a0 = __ldg(&f16[r0]), b0 = __ldg(&f16[r0 + 1]);
        fma16h(a0, b0, __float2half2_rn(__int_as_float(e0.y)), acc);
    }
    int4 o0, o1;
    o0.x = *(int*)&acc[0]; o0.y = *(int*)&acc[1];
    o0.z = *(int*)&acc[2]; o0.w = *(int*)&acc[3];
    o1.x = *(int*)&acc[4]; o1.y = *(int*)&acc[5];
    o1.z = *(int*)&acc[6]; o1.w = *(int*)&acc[7];
    ((int4*)g_aggh)[(size_t)n * K8 + j2]     = o0;
    ((int4*)g_aggh)[(size_t)n * K8 + j2 + 1] = o1;
}

// ---------------- HMMA GEMM (one side): out = aggh @ W + b ----------------------
__global__ void __launch_bounds__(256) k_gemm_mma(
        int woff, const float* __restrict__ bias,
        int K, int reluOut, int fusePool,
        const int* __restrict__ batch, int side) {
    extern __shared__ __half sm[];
    const int KS = K + 8;
    __half* As  = sm;                     // 128 x KS
    __half* Bhi = As + 128 * KS;          // 96 x KS  ([n][k])
    __half* Blo = Bhi + 96 * KS;
    const int rowBase = blockIdx.x * 128;
    const int tid = threadIdx.x;
    const int K8 = K >> 3;

    const int4* Wh4 = (const int4*)(g_whi + woff + side * (HD * K));
    const int4* Wl4 = (const int4*)(g_wlo + woff + side * (HD * K));
    for (int i = tid; i < HD * K8; i += 256) {
        int r = i / K8, j = i - r * K8;
        *(int4*)&Bhi[r * KS + j * 8] = __ldg(&Wh4[i]);
        *(int4*)&Blo[r * KS + j * 8] = __ldg(&Wl4[i]);
    }
    const int4* Ah = (const int4*)g_aggh;
    for (int i = tid; i < 128 * K8; i += 256) {
        int r = i / K8, j = i - r * K8;
        int row = rowBase + r;
        int4 v = make_int4(0, 0, 0, 0);
        if (row < NN) v = __ldg(&Ah[(size_t)(side * NN + row) * K8 + j]);
        *(int4*)&As[r * KS + j * 8] = v;
    }
    __syncthreads();

    const int warp = tid >> 5;
    const int lane = tid & 31;
    const int g = lane >> 2;
    const int tg = lane & 3;
    const int warpRow = warp * 16;

    float c[12][4];
#pragma unroll
    for (int nt = 0; nt < 12; nt++)
#pragma unroll
        for (int q = 0; q < 4; q++) c[nt][q] = 0.f;

    const int nk = K >> 4;
    for (int ks = 0; ks < nk; ks++) {
        unsigned a[4];
        const __half* arow0 = &As[(warpRow + g) * KS + ks * 16 + tg * 2];
        const __half* arow1 = arow0 + 8 * KS;
        a[0] = *(const unsigned*)arow0;
        a[1] = *(const unsigned*)arow1;
        a[2] = *(const unsigned*)(arow0 + 8);
        a[3] = *(const unsigned*)(arow1 + 8);
#pragma unroll
        for (int nt = 0; nt < 12; nt++) {
            const __half* brow = &Bhi[(nt * 8 + g) * KS + ks * 16 + tg * 2];
            unsigned b0 = *(const unsigned*)brow;
            unsigned b1 = *(const unsigned*)(brow + 8);
            mma16816(c[nt], a, b0, b1);
            const __half* brl = &Blo[(nt * 8 + g) * KS + ks * 16 + tg * 2];
            unsigned l0 = *(const unsigned*)brl;
            unsigned l1 = *(const unsigned*)(brl + 8);
            mma16816(c[nt], a, l0, l1);
        }
    }

    int row0 = rowBase + warpRow + g;
    int row1 = row0 + 8;
#pragma unroll
    for (int nt = 0; nt < 12; nt++) {
        int col = nt * 8 + tg * 2;
        float bx = __ldg(&bias[col]);
        float by = __ldg(&bias[col + 1]);
        float v00 = c[nt][0] + bx, v01 = c[nt][1] + by;
        float v10 = c[nt][2] + bx, v11 = c[nt][3] + by;
        if (!fusePool) {
            if (reluOut) {
                v00 = fmaxf(v00, 0.f); v01 = fmaxf(v01, 0.f);
                v10 = fmaxf(v10, 0.f); v11 = fmaxf(v11, 0.f);
            }
            if (row0 < NN) {
                __half2 h = __floats2half2_rn(v00, v01);
                *(unsigned*)&g_hh[(size_t)(side * NN + row0) * HD + col] = *(unsigned*)&h;
            }
            if (row1 < NN) {
                __half2 h = __floats2half2_rn(v10, v11);
                *(unsigned*)&g_hh[(size_t)(side * NN + row1) * HD + col] = *(unsigned*)&h;
            }
        } else {
            if (row0 < NN) red2(&g_z.pool[side][batch[row0] * HD + col], v00, v01);
            if (row1 < NN) red2(&g_z.pool[side][batch[row1] * HD + col], v10, v11);
        }
    }
}

// ---------------- final MLP ---------------------------------------------------
__global__ void k_final(const float* __restrict__ lW0, const float* __restrict__ lb0,
                        const float* __restrict__ lW1, const float* __restrict__ lb1,
                        float* __restrict__ out) {
    int g = blockIdx.x;
    int j = threadIdx.x;                                 // 96 threads
    __shared__ float cat[2 * HD + 2 * FIN];              // 320
    __shared__ float red[HD];
    for (int i = j; i < 2 * HD + 2 * FIN; i += HD) {
        float v;
        if (i < HD)            v = g_z.pool[0][g * HD + i] / fmaxf((float)g_z.cnt[0][g], 1.f);
        else if (i < 2 * HD)   v = g_z.pool[1][g * HD + (i - HD)] / fmaxf((float)g_z.cnt[1][g], 1.f);
        else if (i < 2 * HD + FIN) v = g_z.att[0][g * FIN + (i - 2 * HD)];
        else                   v = g_z.att[1][g * FIN + (i - 2 * HD - FIN)];
        cat[i] = v;
    }
    __syncthreads();
    float acc = lb0[j];
#pragma unroll 8
    for (int i = 0; i < 2 * HD + 2 * FIN; i++)
        acc += cat[i] * lW0[i * HD + j];
    red[j] = fmaxf(acc, 0.f) * lW1[j];
    __syncthreads();
    if (j == 0) {
        float s = lb1[0];
        for (int t = 0; t < HD; t++) s += red[t];
        out[g] = s;
    }
}

// ---------------- host launcher ----------------------------------------------
extern "C" void kernel_launch(void* const* d_in, const int* in_sizes, int n_in,
                              void* d_out, int out_size) {
    const float* xp  = (const float*)d_in[0];
    const float* xd  = (const float*)d_in[1];
    const int*   eip = (const int*)d_in[4];
    const int*   eid = (const int*)d_in[5];
    const int*   bp  = (const int*)d_in[6];
    const int*   bd  = (const int*)d_in[7];
    const float* Wp0 = (const float*)d_in[8],  *bp0 = (const float*)d_in[9];
    const float* Wp1 = (const float*)d_in[10], *bp1 = (const float*)d_in[11];
    const float* Wp2 = (const float*)d_in[12], *bp2 = (const float*)d_in[13];
    const float* Wd0 = (const float*)d_in[14], *bd0 = (const float*)d_in[15];
    const float* Wd1 = (const float*)d_in[16], *bd1 = (const float*)d_in[17];
    const float* Wd2 = (const float*)d_in[18], *bd2 = (const float*)d_in[19];
    const float* gW1 = (const float*)d_in[20], *gb1 = (const float*)d_in[21];
    const float* gW2 = (const float*)d_in[22], *gb2 = (const float*)d_in[23];
    const float* lW0 = (const float*)d_in[24], *lb0 = (const float*)d_in[25];
    const float* lW1 = (const float*)d_in[26], *lb1 = (const float*)d_in[27];

    const int TB = 256;
    const int GB_E = (NE + TB - 1) / TB;             // per-side edge grid
    const int GB_C16 = (NN2 * 16 + TB - 1) / TB;
    const int GB_S4  = (NN * 4 + TB - 1) / TB;       // per-side gather U=4 (K=64)
    const int GB_S6  = (NN * 6 + TB - 1) / TB;       // per-side gather U=6 (K=96)
    const int GEMM_GRID = 391;                       // per-side tiles
    const int SMEM96 = (128 + 96 + 96) * (96 + 8) * 2;   // 66560 B
    const int SMEM64 = (128 + 96 + 96) * (64 + 8) * 2;   // 46080 B

    static cudaStream_t sB = nullptr, sC = nullptr;
    static cudaEvent_t ev1 = nullptr, evT = nullptr, evB = nullptr, evC = nullptr;
    static int inited = 0;
    if (!inited) {
        cudaFuncSetAttribute(k_gemm_mma, cudaFuncAttributeMaxDynamicSharedMemorySize, SMEM96);
        cudaStreamCreateWithFlags(&sB, cudaStreamNonBlocking);
        cudaStreamCreateWithFlags(&sC, cudaStreamNonBlocking);
        cudaEventCreateWithFlags(&ev1, cudaEventDisableTiming);
        cudaEventCreateWithFlags(&evT, cudaEventDisableTiming);
        cudaEventCreateWithFlags(&evB, cudaEventDisableTiming);
        cudaEventCreateWithFlags(&evC, cudaEventDisableTiming);
        inited = 1;
    }

    void* xh_dev = nullptr;  cudaGetSymbolAddress(&xh_dev, g_xh);
    void* hh_dev = nullptr;  cudaGetSymbolAddress(&hh_dev, g_hh);
    void* deg_dev = nullptr; cudaGetSymbolAddress(&deg_dev, g_deg);
    void* z_dev = nullptr;   cudaGetSymbolAddress(&z_dev, g_z);

    // ---- fork ----
    cudaEventRecord(ev1, 0);
    cudaStreamWaitEvent(sB, ev1, 0);
    cudaStreamWaitEvent(sC, ev1, 0);

    // stream B: zero-init, weight prep + tohalf, then gate+attpool
    cudaMemsetAsync(z_dev, 0, sizeof(ZeroBlk), sB);
    k_prepw<<<(WTOT + TB - 1) / TB, TB, 0, sB>>>(Wp0, Wd0, Wp1, Wd1, Wp2, Wd2);
    k_tohalf<<<GB_C16, TB, 0, sB>>>((const float4*)xp, (const float4*)xd);
    cudaEventRecord(evT, sB);                 // side chains need prepw+tohalf
    k_gate<<<(NN2 + 7) / 8, 256, 0, sB>>>(xp, xd, bp, bd, gW1, gb1, gW2, gb2);
    k_attpool<<<GB_C16, TB, 0, sB>>>(xp, xd, bp, bd);
    cudaEventRecord(evB, sB);                 // k_final needs this

    // stream A (default): side-p CSR + chain
    cudaMemsetAsync(deg_dev, 0, NN * sizeof(int), 0);
    k_deg_s<<<GB_E, TB>>>(eip, 0);
    k_scan1_s<<<NSCB, SCB>>>(0);
    k_scan3_s<<<NSCB, SCB>>>(0);
    k_csrfill_s<<<GB_E, TB>>>(eip, 0);
    cudaStreamWaitEvent(0, evT, 0);
    k_gatherh<<<GB_S4, TB>>>((const int4*)xh_dev, 8, 0);
    k_gemm_mma<<<GEMM_GRID, 256, SMEM64>>>(WOFF_L0, bp0, 64, 1, 0, bp, 0);
    k_gatherh<<<GB_S6, TB>>>((const int4*)hh_dev, 12, 0);
    k_gemm_mma<<<GEMM_GRID, 256, SMEM96>>>(WOFF_L1, bp1, 96, 1, 0, bp, 0);
    k_gatherh<<<GB_S6, TB>>>((const int4*)hh_dev, 12, 0);
    k_gemm_mma<<<GEMM_GRID, 256, SMEM96>>>(WOFF_L2, bp2, 96, 0, 1, bp, 0);

    // stream C: side-d CSR + chain (fully independent of side-p)
    cudaMemsetAsync((char*)deg_dev + NN * sizeof(int), 0, NN * sizeof(int), sC);
    k_deg_s<<<GB_E, TB, 0, sC>>>(eid, 1);
    k_scan1_s<<<NSCB, SCB, 0, sC>>>(1);
    k_scan3_s<<<NSCB, SCB, 0, sC>>>(1);
    k_csrfill_s<<<GB_E, TB, 0, sC>>>(eid, 1);
    cudaStreamWaitEvent(sC, evT, 0);
    k_gatherh<<<GB_S4, TB, 0, sC>>>((const int4*)xh_dev, 8, 1);
    k_gemm_mma<<<GEMM_GRID, 256, SMEM64, sC>>>(WOFF_L0, bd0, 64, 1, 0, bd, 1);
    k_gatherh<<<GB_S6, TB, 0, sC>>>((const int4*)hh_dev, 12, 1);
    k_gemm_mma<<<GEMM_GRID, 256, SMEM96, sC>>>(WOFF_L1, bd1, 96, 1, 0, bd, 1);
    k_gatherh<<<GB_S6, TB, 0, sC>>>((const int4*)hh_dev, 12, 1);
    k_gemm_mma<<<GEMM_GRID, 256, SMEM96, sC>>>(WOFF_L2, bd2, 96, 0, 1, bd, 1);
    cudaEventRecord(evC, sC);

    // join: k_final needs side-p (stream A order), side-d (evC), attpool (evB)
    cudaStreamWaitEvent(0, evC, 0);
    cudaStreamWaitEvent(0, evB, 0);
    k_final<<<NG, HD>>>(lW0, lb0, lW1, lb1, (float*)d_out);
}